// round 15
// baseline (speedup 1.0000x reference)
#include <cuda_runtime.h>
#include <cuda_fp16.h>
#include <cstdint>

// GCN via mma.sync FP16 (m16n8k16, fp32 accumulate) + ldmatrix + cp.async.
// R14 = R13 (assoc-optimized chain, champion 160x128/4-warp/occ-2 GEMM)
// with ONE change: the s-step body interleaves B-fragment ldmatrix with the
// MMA stream (load b[0] + A first, then per-nt: prefetch b[nt+1] while the
// 5 MMAs of column nt issue) -- shortens the ldsm->mma critical path.
// adj pre-scaled by 2^14 into fp16 normal range (exact 2^-14 unscale).

#define NNODES 10000
#define A_BYTES 20480               // 160 rows x 128 B
#define STAGE_BYTES 36864           // A 20KB + B 16KB
#define SMEM_TOTAL (3 * STAGE_BYTES)

__device__ __half g_adjh[(size_t)NNODES * (size_t)NNODES];
__device__ __half g_bufA[(size_t)NNODES * 1024];
__device__ __half g_bufB[(size_t)NNODES * 1024];
__device__ __half g_wts[1310720];
#define O_W1T 0
#define O_W2T 262144
#define O_W3T 524288
#define O_WFT 1048576

__device__ __forceinline__ uint32_t smem_u32(const void* p) {
    uint32_t a;
    asm("{ .reg .u64 t; cvta.to.shared.u64 t, %1; cvt.u32.u64 %0, t; }"
        : "=r"(a) : "l"(p));
    return a;
}

__device__ __forceinline__ void cpa16(uint32_t dst, const __half* src, int bytes) {
    asm volatile("cp.async.cg.shared.global [%0], [%1], 16, %2;"
                 :: "r"(dst), "l"(src), "r"(bytes) : "memory");
}
#define CP_COMMIT() asm volatile("cp.async.commit_group;" ::: "memory")
#define CP_WAIT1()  asm volatile("cp.async.wait_group 1;" ::: "memory")
#define CP_WAIT0()  asm volatile("cp.async.wait_group 0;" ::: "memory")

__device__ __forceinline__ void ldsm4(uint32_t* r, uint32_t a) {
    asm volatile("ldmatrix.sync.aligned.m8n8.x4.shared.b16 {%0,%1,%2,%3}, [%4];"
                 : "=r"(r[0]), "=r"(r[1]), "=r"(r[2]), "=r"(r[3]) : "r"(a));
}
__device__ __forceinline__ void ldsm2(uint32_t* r, uint32_t a) {
    asm volatile("ldmatrix.sync.aligned.m8n8.x2.shared.b16 {%0,%1}, [%2];"
                 : "=r"(r[0]), "=r"(r[1]) : "r"(a));
}
__device__ __forceinline__ void mma16(float* c, const uint32_t* a, const uint32_t* b) {
    asm volatile("mma.sync.aligned.m16n8k16.row.col.f32.f16.f16.f32 "
                 "{%0,%1,%2,%3}, {%4,%5,%6,%7}, {%8,%9}, {%0,%1,%2,%3};"
                 : "+f"(c[0]), "+f"(c[1]), "+f"(c[2]), "+f"(c[3])
                 : "r"(a[0]), "r"(a[1]), "r"(a[2]), "r"(a[3]),
                   "r"(b[0]), "r"(b[1]));
}

// C = A[M,K] @ B_nk[N,K]^T ; A,B fp16 row-major, leading dim K (halves).
// CTA tile 160x128, 4 warps (80x64 each). TRANS: write C^T; SCALE: *2^-14;
// OUTF32: fp32 out else fp16 RN.
template <int TRANS, int BIAS, int RELU, int SCALE, int OUTF32>
__global__ void __launch_bounds__(128, 2)
tc_gemm(const __half* __restrict__ A, const __half* __restrict__ B,
        const float* __restrict__ bias, void* __restrict__ Cv,
        int M, int N, int K) {
    extern __shared__ char smem[];
    const uint32_t sb = smem_u32(smem);
    const int tid = threadIdx.x;
    const int lane = tid & 31, w = tid >> 5;
    const int warp_m = (w & 1) * 80, warp_n = (w >> 1) * 64;
    const int rowBase = blockIdx.y * 160, colBase = blockIdx.x * 128;

    // ---- loader: 128 threads; r = tid>>3 (0..15), 16B chunk col = tid&7
    const int ldr = tid >> 3;
    const int ldc8 = (tid & 7) * 8;  // half offset
    const uint32_t dstBase = (uint32_t)(ldr * 128) +
                             (uint32_t)(((tid & 7) ^ (ldr & 7)) * 16);
    const __half* aBase = A + (size_t)(rowBase + ldr) * K + ldc8;
    const __half* bBase = B + (size_t)(colBase + ldr) * K + ldc8;
    const size_t K16 = (size_t)K * 16;   // 16-row stride (halves)

    const int nc = (K + 63) >> 6;

    auto issue = [&](int c) {
        const uint32_t st = sb + (uint32_t)(c % 3) * STAGE_BYTES;
        const int k0 = c * 64;
        const bool kok = (k0 + ldc8) < K;
#pragma unroll
        for (int i = 0; i < 10; i++) {  // A: 160 rows (16-row steps)
            bool v = kok && (rowBase + ldr + 16 * i) < M;
            cpa16(st + dstBase + (uint32_t)i * 2048,
                  aBase + k0 + (size_t)i * K16, v ? 16 : 0);
        }
#pragma unroll
        for (int i = 0; i < 8; i++) {   // B: 128 rows
            bool v = kok && (colBase + ldr + 16 * i) < N;
            cpa16(st + A_BYTES + dstBase + (uint32_t)i * 2048,
                  bBase + k0 + (size_t)i * K16, v ? 16 : 0);
        }
        CP_COMMIT();
    };

    issue(0);
    issue(1);

    // ---- fragment addressing (proven 128B-row swizzle) ----
    const int l8 = lane & 7;
    const int l16 = lane & 15;
    const uint32_t aLdRow = (uint32_t)(warp_m + l8 + ((lane >> 3) & 1) * 8) * 128;
    const uint32_t bLdRow = (uint32_t)(warp_n + (l16 & 7)) * 128;
    uint32_t aChunk[4], bChunk[4];
#pragma unroll
    for (int s = 0; s < 4; s++) {
        aChunk[s] = (uint32_t)(((s * 2 + (lane >> 4)) ^ l8) * 16);
        bChunk[s] = (uint32_t)(((s * 2 + (l16 >> 3)) ^ (l16 & 7)) * 16);
    }

    float cr[5][8][4];
#pragma unroll
    for (int mt = 0; mt < 5; mt++)
#pragma unroll
        for (int nt = 0; nt < 8; nt++)
#pragma unroll
            for (int r = 0; r < 4; r++) cr[mt][nt][r] = 0.f;

    for (int c = 0; c < nc; c++) {
        CP_WAIT1();
        __syncthreads();
        if (c + 2 < nc) issue(c + 2); else CP_COMMIT();

        const uint32_t sA = sb + (uint32_t)(c % 3) * STAGE_BYTES;
        const uint32_t sB = sA + A_BYTES;
#pragma unroll
        for (int s = 0; s < 4; s++) {   // each s-step = k16
            uint32_t a[5][4], b[8][2];
            // b[0] first (earliest mma dependency), then A frags
            ldsm2(b[0], sB + bLdRow + 0 * 1024 + bChunk[s]);
#pragma unroll
            for (int mt = 0; mt < 5; mt++)
                ldsm4(a[mt], sA + aLdRow + mt * 2048 + aChunk[s]);
            // interleave: prefetch b[nt+1] while column nt's 5 MMAs issue
#pragma unroll
            for (int nt = 0; nt < 8; nt++) {
                if (nt < 7)
                    ldsm2(b[nt + 1], sB + bLdRow + (uint32_t)(nt + 1) * 1024 + bChunk[s]);
#pragma unroll
                for (int mt = 0; mt < 5; mt++)
                    mma16(cr[mt][nt], a[mt], b[nt]);
            }
        }
    }
    CP_WAIT0();

    // ---- epilogue ----
    const int g = lane >> 2, t = lane & 3;
#pragma unroll
    for (int mt = 0; mt < 5; mt++) {
        const int m0 = rowBase + warp_m + mt * 16 + g;
#pragma unroll
        for (int nt = 0; nt < 8; nt++) {
            const int n0 = colBase + warp_n + nt * 8 + 2 * t;
            float v0 = cr[mt][nt][0], v1 = cr[mt][nt][1];
            float v2 = cr[mt][nt][2], v3 = cr[mt][nt][3];
            if (SCALE) {   // undo adj pre-scale by 2^14 (exact)
                const float s = 6.103515625e-5f;
                v0 *= s; v1 *= s; v2 *= s; v3 *= s;
            }
            if (BIAS) {
                float bb0 = (n0 < N) ? bias[n0] : 0.f;
                float bb1 = (n0 + 1 < N) ? bias[n0 + 1] : 0.f;
                v0 += bb0; v1 += bb1; v2 += bb0; v3 += bb1;
            }
            if (RELU) {
                v0 = fmaxf(v0, 0.f); v1 = fmaxf(v1, 0.f);
                v2 = fmaxf(v2, 0.f); v3 = fmaxf(v3, 0.f);
            }
            if (OUTF32) {
                float* C = (float*)Cv;
                if (m0 < M) {
                    if (n0 < N)     C[(size_t)m0 * N + n0] = v0;
                    if (n0 + 1 < N) C[(size_t)m0 * N + n0 + 1] = v1;
                }
                if (m0 + 8 < M) {
                    if (n0 < N)     C[(size_t)(m0 + 8) * N + n0] = v2;
                    if (n0 + 1 < N) C[(size_t)(m0 + 8) * N + n0 + 1] = v3;
                }
            } else if (TRANS) {
                __half* C = (__half*)Cv;
                if (n0 < N) {
                    if (m0 < M)     C[(size_t)n0 * M + m0] = __float2half_rn(v0);
                    if (m0 + 8 < M) C[(size_t)n0 * M + m0 + 8] = __float2half_rn(v2);
                }
                if (n0 + 1 < N) {
                    if (m0 < M)     C[(size_t)(n0 + 1) * M + m0] = __float2half_rn(v1);
                    if (m0 + 8 < M) C[(size_t)(n0 + 1) * M + m0 + 8] = __float2half_rn(v3);
                }
            } else {
                __half* C = (__half*)Cv;
                if (m0 < M) {
                    if (n0 < N)     C[(size_t)m0 * N + n0] = __float2half_rn(v0);
                    if (n0 + 1 < N) C[(size_t)m0 * N + n0 + 1] = __float2half_rn(v1);
                }
                if (m0 + 8 < M) {
                    if (n0 < N)     C[(size_t)(m0 + 8) * N + n0] = __float2half_rn(v2);
                    if (n0 + 1 < N) C[(size_t)(m0 + 8) * N + n0 + 1] = __float2half_rn(v3);
                }
            }
        }
    }
}

// ---------------- prep kernels (merged; float4 vectorized) -----------------
__global__ void cvt_both_kernel(const float4* __restrict__ adj, __half2* __restrict__ adjh,
                                size_t nA4,
                                const float4* __restrict__ x, __half2* __restrict__ xh,
                                size_t nX4) {
    size_t i = (size_t)blockIdx.x * blockDim.x + threadIdx.x;
    size_t stride = (size_t)gridDim.x * blockDim.x;
    for (; i < nA4 + nX4; i += stride) {
        if (i < nA4) {
            float4 v = adj[i];
            adjh[i * 2]     = __floats2half2_rn(v.x * 16384.f, v.y * 16384.f);
            adjh[i * 2 + 1] = __floats2half2_rn(v.z * 16384.f, v.w * 16384.f);
        } else {
            size_t j = i - nA4;
            float4 v = x[j];
            xh[j * 2]     = __floats2half2_rn(v.x, v.y);
            xh[j * 2 + 1] = __floats2half2_rn(v.z, v.w);
        }
    }
}

__global__ void transpose_cvt4(const float* __restrict__ in0, __half* __restrict__ out0, int R0, int C0,
                               const float* __restrict__ in1, __half* __restrict__ out1, int R1, int C1,
                               const float* __restrict__ in2, __half* __restrict__ out2, int R2, int C2,
                               const float* __restrict__ in3, __half* __restrict__ out3, int R3, int C3) {
    const float* in; __half* out; int R, Cc;
    switch (blockIdx.z) {
        case 0: in = in0; out = out0; R = R0; Cc = C0; break;
        case 1: in = in1; out = out1; R = R1; Cc = C1; break;
        case 2: in = in2; out = out2; R = R2; Cc = C2; break;
        default: in = in3; out = out3; R = R3; Cc = C3; break;
    }
    int c0 = blockIdx.x * 32, r0 = blockIdx.y * 32;
    if (c0 >= Cc || r0 >= R) return;
    __shared__ float tbuf[32][33];
    int tx = threadIdx.x, ty = threadIdx.y;  // 32x8
#pragma unroll
    for (int j = 0; j < 4; j++) {
        int r = r0 + ty + j * 8, c = c0 + tx;
        tbuf[ty + j * 8][tx] = (r < R && c < Cc) ? in[(size_t)r * Cc + c] : 0.f;
    }
    __syncthreads();
#pragma unroll
    for (int j = 0; j < 4; j++) {
        int c = c0 + ty + j * 8, r = r0 + tx;
        if (c < Cc && r < R) out[(size_t)c * R + r] = __float2half_rn(tbuf[tx][ty + j * 8]);
    }
}

// ---------------- launch ----------------------------------------------------
static inline dim3 gmk(int M, int N) {
    return dim3((unsigned)((N + 127) / 128), (unsigned)((M + 159) / 160), 1);
}

extern "C" void kernel_launch(void* const* d_in, const int* in_sizes, int n_in,
                              void* d_out, int out_size) {
    const float* x   = (const float*)d_in[0];
    const float* adj = (const float*)d_in[1];
    const float* W1  = (const float*)d_in[2];
    const float* b1  = (const float*)d_in[3];
    const float* W2  = (const float*)d_in[4];
    const float* b2  = (const float*)d_in[5];
    const float* W3  = (const float*)d_in[6];
    const float* b3  = (const float*)d_in[7];
    const float* Wf  = (const float*)d_in[8];
    const float* bf  = (const float*)d_in[9];
    float* out = (float*)d_out;

    __half *adjh, *bufA, *bufB, *wts;
    cudaGetSymbolAddress((void**)&adjh, g_adjh);
    cudaGetSymbolAddress((void**)&bufA, g_bufA);
    cudaGetSymbolAddress((void**)&bufB, g_bufB);
    cudaGetSymbolAddress((void**)&wts, g_wts);

    cudaFuncSetAttribute(tc_gemm<1, 0, 0, 0, 0>, cudaFuncAttributeMaxDynamicSharedMemorySize, SMEM_TOTAL);
    cudaFuncSetAttribute(tc_gemm<0, 1, 1, 1, 0>, cudaFuncAttributeMaxDynamicSharedMemorySize, SMEM_TOTAL);
    cudaFuncSetAttribute(tc_gemm<1, 1, 1, 1, 0>, cudaFuncAttributeMaxDynamicSharedMemorySize, SMEM_TOTAL);
    cudaFuncSetAttribute(tc_gemm<0, 0, 0, 1, 0>, cudaFuncAttributeMaxDynamicSharedMemorySize, SMEM_TOTAL);
    cudaFuncSetAttribute(tc_gemm<0, 1, 1, 0, 0>, cudaFuncAttributeMaxDynamicSharedMemorySize, SMEM_TOTAL);
    cudaFuncSetAttribute(tc_gemm<0, 1, 0, 0, 1>, cudaFuncAttributeMaxDynamicSharedMemorySize, SMEM_TOTAL);

    const int M = NNODES;

    // launch 1: all weight transposes (batched)
    transpose_cvt4<<<dim3(32, 32, 4), dim3(32, 8)>>>(
        W1, wts + O_W1T, 512, 512,  W2, wts + O_W2T, 512, 512,
        W3, wts + O_W3T, 512, 1024, Wf, wts + O_WFT, 1024, 151);
    // launch 2: adj (x 2^14) + x -> fp16 (x lands in bufA)
    cvt_both_kernel<<<8192, 256>>>((const float4*)adj, (__half2*)adjh, (size_t)M * M / 4,
                                   (const float4*)x, (__half2*)bufA, (size_t)M * 512 / 4);

    // launch 3 — F1: bufB = (x @ W1)^T             [512 x 10000]
    tc_gemm<1, 0, 0, 0, 0><<<gmk(M, 512), 128, SMEM_TOTAL>>>(bufA, wts + O_W1T, nullptr, bufB, M, 512, 512);
    // launch 4 — G1: bufA = relu(adj @ P1 + b1)    [10000 x 512]   (ncu)
    tc_gemm<0, 1, 1, 1, 0><<<gmk(M, 512), 128, SMEM_TOTAL>>>(adjh, bufB, b1, bufA, M, 512, M);
    // F2: bufB = (H1 @ W2)^T                       [512 x 10000]
    tc_gemm<1, 0, 0, 0, 0><<<gmk(M, 512), 128, SMEM_TOTAL>>>(bufA, wts + O_W2T, nullptr, bufB, M, 512, 512);
    // G2: bufA = relu(adj @ P2 + b2)^T             [512 x 10000]  (TRANS write)
    tc_gemm<1, 1, 1, 1, 0><<<gmk(M, 512), 128, SMEM_TOTAL>>>(adjh, bufB, b2, bufA, M, 512, M);
    // G3': bufB = adj @ H2                         [10000 x 512]  (assoc. trick)
    tc_gemm<0, 0, 0, 1, 0><<<gmk(M, 512), 128, SMEM_TOTAL>>>(adjh, bufA, nullptr, bufB, M, 512, M);
    // F3': bufA = relu(Q @ W3 + b3)                [10000 x 1024]
    tc_gemm<0, 1, 1, 0, 0><<<gmk(M, 1024), 128, SMEM_TOTAL>>>(bufB, wts + O_W3T, b3, bufA, M, 1024, 512);
    // F4: out = H3 @ Wf + bf                       [10000 x 151] fp32
    tc_gemm<0, 1, 0, 0, 1><<<gmk(M, 151), 128, SMEM_TOTAL>>>(bufA, wts + O_WFT, bf, out, M, 151, 1024);
}

// round 17
// speedup vs baseline: 1.0624x; 1.0624x over previous
#include <cuda_runtime.h>
#include <cuda_fp16.h>
#include <cstdint>

// GCN via mma.sync FP16 (m16n8k16, fp32 accumulate) + ldmatrix + cp.async.
// R16 = R13 champion GEMM body (plain load-then-mma s-steps; scheduling
// variants R11/R12/R14 all regressed) + __half2-packed fp16 epilogue stores.
// OUTF32 path uses SCALAR stores: F4 has N=151 (odd) so float2 would be
// misaligned for odd rows (R15's crash).
// adj pre-scaled by 2^14 into fp16 normal range (exact 2^-14 unscale).

#define NNODES 10000
#define A_BYTES 20480               // 160 rows x 128 B
#define STAGE_BYTES 36864           // A 20KB + B 16KB
#define SMEM_TOTAL (3 * STAGE_BYTES)

__device__ __half g_adjh[(size_t)NNODES * (size_t)NNODES];
__device__ __half g_bufA[(size_t)NNODES * 1024];
__device__ __half g_bufB[(size_t)NNODES * 1024];
__device__ __half g_wts[1310720];
#define O_W1T 0
#define O_W2T 262144
#define O_W3T 524288
#define O_WFT 1048576

__device__ __forceinline__ uint32_t smem_u32(const void* p) {
    uint32_t a;
    asm("{ .reg .u64 t; cvta.to.shared.u64 t, %1; cvt.u32.u64 %0, t; }"
        : "=r"(a) : "l"(p));
    return a;
}

__device__ __forceinline__ void cpa16(uint32_t dst, const __half* src, int bytes) {
    asm volatile("cp.async.cg.shared.global [%0], [%1], 16, %2;"
                 :: "r"(dst), "l"(src), "r"(bytes) : "memory");
}
#define CP_COMMIT() asm volatile("cp.async.commit_group;" ::: "memory")
#define CP_WAIT1()  asm volatile("cp.async.wait_group 1;" ::: "memory")
#define CP_WAIT0()  asm volatile("cp.async.wait_group 0;" ::: "memory")

__device__ __forceinline__ void ldsm4(uint32_t* r, uint32_t a) {
    asm volatile("ldmatrix.sync.aligned.m8n8.x4.shared.b16 {%0,%1,%2,%3}, [%4];"
                 : "=r"(r[0]), "=r"(r[1]), "=r"(r[2]), "=r"(r[3]) : "r"(a));
}
__device__ __forceinline__ void ldsm2(uint32_t* r, uint32_t a) {
    asm volatile("ldmatrix.sync.aligned.m8n8.x2.shared.b16 {%0,%1}, [%2];"
                 : "=r"(r[0]), "=r"(r[1]) : "r"(a));
}
__device__ __forceinline__ void mma16(float* c, const uint32_t* a, const uint32_t* b) {
    asm volatile("mma.sync.aligned.m16n8k16.row.col.f32.f16.f16.f32 "
                 "{%0,%1,%2,%3}, {%4,%5,%6,%7}, {%8,%9}, {%0,%1,%2,%3};"
                 : "+f"(c[0]), "+f"(c[1]), "+f"(c[2]), "+f"(c[3])
                 : "r"(a[0]), "r"(a[1]), "r"(a[2]), "r"(a[3]),
                   "r"(b[0]), "r"(b[1]));
}

// C = A[M,K] @ B_nk[N,K]^T ; A,B fp16 row-major, leading dim K (halves).
// CTA tile 160x128, 4 warps (80x64 each). TRANS: write C^T; SCALE: *2^-14;
// OUTF32: fp32 out else fp16 RN.
template <int TRANS, int BIAS, int RELU, int SCALE, int OUTF32>
__global__ void __launch_bounds__(128, 2)
tc_gemm(const __half* __restrict__ A, const __half* __restrict__ B,
        const float* __restrict__ bias, void* __restrict__ Cv,
        int M, int N, int K) {
    extern __shared__ char smem[];
    const uint32_t sb = smem_u32(smem);
    const int tid = threadIdx.x;
    const int lane = tid & 31, w = tid >> 5;
    const int warp_m = (w & 1) * 80, warp_n = (w >> 1) * 64;
    const int rowBase = blockIdx.y * 160, colBase = blockIdx.x * 128;

    // ---- loader: 128 threads; r = tid>>3 (0..15), 16B chunk col = tid&7
    const int ldr = tid >> 3;
    const int ldc8 = (tid & 7) * 8;  // half offset
    const uint32_t dstBase = (uint32_t)(ldr * 128) +
                             (uint32_t)(((tid & 7) ^ (ldr & 7)) * 16);
    const __half* aBase = A + (size_t)(rowBase + ldr) * K + ldc8;
    const __half* bBase = B + (size_t)(colBase + ldr) * K + ldc8;
    const size_t K16 = (size_t)K * 16;   // 16-row stride (halves)

    const int nc = (K + 63) >> 6;

    auto issue = [&](int c) {
        const uint32_t st = sb + (uint32_t)(c % 3) * STAGE_BYTES;
        const int k0 = c * 64;
        const bool kok = (k0 + ldc8) < K;
#pragma unroll
        for (int i = 0; i < 10; i++) {  // A: 160 rows (16-row steps)
            bool v = kok && (rowBase + ldr + 16 * i) < M;
            cpa16(st + dstBase + (uint32_t)i * 2048,
                  aBase + k0 + (size_t)i * K16, v ? 16 : 0);
        }
#pragma unroll
        for (int i = 0; i < 8; i++) {   // B: 128 rows
            bool v = kok && (colBase + ldr + 16 * i) < N;
            cpa16(st + A_BYTES + dstBase + (uint32_t)i * 2048,
                  bBase + k0 + (size_t)i * K16, v ? 16 : 0);
        }
        CP_COMMIT();
    };

    issue(0);
    issue(1);

    // ---- fragment addressing (proven 128B-row swizzle) ----
    const int l8 = lane & 7;
    const int l16 = lane & 15;
    const uint32_t aLdRow = (uint32_t)(warp_m + l8 + ((lane >> 3) & 1) * 8) * 128;
    const uint32_t bLdRow = (uint32_t)(warp_n + (l16 & 7)) * 128;
    uint32_t aChunk[4], bChunk[4];
#pragma unroll
    for (int s = 0; s < 4; s++) {
        aChunk[s] = (uint32_t)(((s * 2 + (lane >> 4)) ^ l8) * 16);
        bChunk[s] = (uint32_t)(((s * 2 + (l16 >> 3)) ^ (l16 & 7)) * 16);
    }

    float cr[5][8][4];
#pragma unroll
    for (int mt = 0; mt < 5; mt++)
#pragma unroll
        for (int nt = 0; nt < 8; nt++)
#pragma unroll
            for (int r = 0; r < 4; r++) cr[mt][nt][r] = 0.f;

    for (int c = 0; c < nc; c++) {
        CP_WAIT1();
        __syncthreads();
        if (c + 2 < nc) issue(c + 2); else CP_COMMIT();

        const uint32_t sA = sb + (uint32_t)(c % 3) * STAGE_BYTES;
        const uint32_t sB = sA + A_BYTES;
#pragma unroll
        for (int s = 0; s < 4; s++) {   // each s-step = k16
            uint32_t a[5][4], b[8][2];
#pragma unroll
            for (int mt = 0; mt < 5; mt++)
                ldsm4(a[mt], sA + aLdRow + mt * 2048 + aChunk[s]);
#pragma unroll
            for (int nt = 0; nt < 8; nt++)
                ldsm2(b[nt], sB + bLdRow + nt * 1024 + bChunk[s]);
#pragma unroll
            for (int mt = 0; mt < 5; mt++)
#pragma unroll
                for (int nt = 0; nt < 8; nt++)
                    mma16(cr[mt][nt], a[mt], b[nt]);
        }
    }
    CP_WAIT0();

    // ---- epilogue ----
    const int g = lane >> 2, t = lane & 3;
#pragma unroll
    for (int mt = 0; mt < 5; mt++) {
        const int m0 = rowBase + warp_m + mt * 16 + g;
#pragma unroll
        for (int nt = 0; nt < 8; nt++) {
            const int n0 = colBase + warp_n + nt * 8 + 2 * t;   // always even
            float v0 = cr[mt][nt][0], v1 = cr[mt][nt][1];
            float v2 = cr[mt][nt][2], v3 = cr[mt][nt][3];
            if (SCALE) {   // undo adj pre-scale by 2^14 (exact)
                const float s = 6.103515625e-5f;
                v0 *= s; v1 *= s; v2 *= s; v3 *= s;
            }
            if (BIAS) {
                float bb0 = (n0 < N) ? bias[n0] : 0.f;
                float bb1 = (n0 + 1 < N) ? bias[n0 + 1] : 0.f;
                v0 += bb0; v1 += bb1; v2 += bb0; v3 += bb1;
            }
            if (RELU) {
                v0 = fmaxf(v0, 0.f); v1 = fmaxf(v1, 0.f);
                v2 = fmaxf(v2, 0.f); v3 = fmaxf(v3, 0.f);
            }
            if (OUTF32) {
                // scalar stores: N may be odd (F4: N=151) -> float2 can trap
                float* C = (float*)Cv;
                if (m0 < M) {
                    if (n0 < N)     C[(size_t)m0 * N + n0] = v0;
                    if (n0 + 1 < N) C[(size_t)m0 * N + n0 + 1] = v1;
                }
                if (m0 + 8 < M) {
                    if (n0 < N)     C[(size_t)(m0 + 8) * N + n0] = v2;
                    if (n0 + 1 < N) C[(size_t)(m0 + 8) * N + n0 + 1] = v3;
                }
            } else if (TRANS) {
                __half* C = (__half*)Cv;
                if (n0 < N) {
                    if (m0 < M)     C[(size_t)n0 * M + m0] = __float2half_rn(v0);
                    if (m0 + 8 < M) C[(size_t)n0 * M + m0 + 8] = __float2half_rn(v2);
                }
                if (n0 + 1 < N) {
                    if (m0 < M)     C[(size_t)(n0 + 1) * M + m0] = __float2half_rn(v1);
                    if (m0 + 8 < M) C[(size_t)(n0 + 1) * M + m0 + 8] = __float2half_rn(v3);
                }
            } else {
                // fp16 out: N even (512/1024) and n0 even -> half2 aligned
                __half* C = (__half*)Cv;
                const bool nfull = (n0 + 1 < N);
                if (m0 < M) {
                    if (nfull)
                        *(__half2*)(C + (size_t)m0 * N + n0) =
                            __halves2half2(__float2half_rn(v0), __float2half_rn(v1));
                    else if (n0 < N) C[(size_t)m0 * N + n0] = __float2half_rn(v0);
                }
                if (m0 + 8 < M) {
                    if (nfull)
                        *(__half2*)(C + (size_t)(m0 + 8) * N + n0) =
                            __halves2half2(__float2half_rn(v2), __float2half_rn(v3));
                    else if (n0 < N) C[(size_t)(m0 + 8) * N + n0] = __float2half_rn(v2);
                }
            }
        }
    }
}

// ---------------- prep kernels (merged; float4 vectorized) -----------------
__global__ void cvt_both_kernel(const float4* __restrict__ adj, __half2* __restrict__ adjh,
                                size_t nA4,
                                const float4* __restrict__ x, __half2* __restrict__ xh,
                                size_t nX4) {
    size_t i = (size_t)blockIdx.x * blockDim.x + threadIdx.x;
    size_t stride = (size_t)gridDim.x * blockDim.x;
    for (; i < nA4 + nX4; i += stride) {
        if (i < nA4) {
            float4 v = adj[i];
            adjh[i * 2]     = __floats2half2_rn(v.x * 16384.f, v.y * 16384.f);
            adjh[i * 2 + 1] = __floats2half2_rn(v.z * 16384.f, v.w * 16384.f);
        } else {
            size_t j = i - nA4;
            float4 v = x[j];
            xh[j * 2]     = __floats2half2_rn(v.x, v.y);
            xh[j * 2 + 1] = __floats2half2_rn(v.z, v.w);
        }
    }
}

__global__ void transpose_cvt4(const float* __restrict__ in0, __half* __restrict__ out0, int R0, int C0,
                               const float* __restrict__ in1, __half* __restrict__ out1, int R1, int C1,
                               const float* __restrict__ in2, __half* __restrict__ out2, int R2, int C2,
                               const float* __restrict__ in3, __half* __restrict__ out3, int R3, int C3) {
    const float* in; __half* out; int R, Cc;
    switch (blockIdx.z) {
        case 0: in = in0; out = out0; R = R0; Cc = C0; break;
        case 1: in = in1; out = out1; R = R1; Cc = C1; break;
        case 2: in = in2; out = out2; R = R2; Cc = C2; break;
        default: in = in3; out = out3; R = R3; Cc = C3; break;
    }
    int c0 = blockIdx.x * 32, r0 = blockIdx.y * 32;
    if (c0 >= Cc || r0 >= R) return;
    __shared__ float tbuf[32][33];
    int tx = threadIdx.x, ty = threadIdx.y;  // 32x8
#pragma unroll
    for (int j = 0; j < 4; j++) {
        int r = r0 + ty + j * 8, c = c0 + tx;
        tbuf[ty + j * 8][tx] = (r < R && c < Cc) ? in[(size_t)r * Cc + c] : 0.f;
    }
    __syncthreads();
#pragma unroll
    for (int j = 0; j < 4; j++) {
        int c = c0 + ty + j * 8, r = r0 + tx;
        if (c < Cc && r < R) out[(size_t)c * R + r] = __float2half_rn(tbuf[tx][ty + j * 8]);
    }
}

// ---------------- launch ----------------------------------------------------
static inline dim3 gmk(int M, int N) {
    return dim3((unsigned)((N + 127) / 128), (unsigned)((M + 159) / 160), 1);
}

extern "C" void kernel_launch(void* const* d_in, const int* in_sizes, int n_in,
                              void* d_out, int out_size) {
    const float* x   = (const float*)d_in[0];
    const float* adj = (const float*)d_in[1];
    const float* W1  = (const float*)d_in[2];
    const float* b1  = (const float*)d_in[3];
    const float* W2  = (const float*)d_in[4];
    const float* b2  = (const float*)d_in[5];
    const float* W3  = (const float*)d_in[6];
    const float* b3  = (const float*)d_in[7];
    const float* Wf  = (const float*)d_in[8];
    const float* bf  = (const float*)d_in[9];
    float* out = (float*)d_out;

    __half *adjh, *bufA, *bufB, *wts;
    cudaGetSymbolAddress((void**)&adjh, g_adjh);
    cudaGetSymbolAddress((void**)&bufA, g_bufA);
    cudaGetSymbolAddress((void**)&bufB, g_bufB);
    cudaGetSymbolAddress((void**)&wts, g_wts);

    cudaFuncSetAttribute(tc_gemm<1, 0, 0, 0, 0>, cudaFuncAttributeMaxDynamicSharedMemorySize, SMEM_TOTAL);
    cudaFuncSetAttribute(tc_gemm<0, 1, 1, 1, 0>, cudaFuncAttributeMaxDynamicSharedMemorySize, SMEM_TOTAL);
    cudaFuncSetAttribute(tc_gemm<1, 1, 1, 1, 0>, cudaFuncAttributeMaxDynamicSharedMemorySize, SMEM_TOTAL);
    cudaFuncSetAttribute(tc_gemm<0, 0, 0, 1, 0>, cudaFuncAttributeMaxDynamicSharedMemorySize, SMEM_TOTAL);
    cudaFuncSetAttribute(tc_gemm<0, 1, 1, 0, 0>, cudaFuncAttributeMaxDynamicSharedMemorySize, SMEM_TOTAL);
    cudaFuncSetAttribute(tc_gemm<0, 1, 0, 0, 1>, cudaFuncAttributeMaxDynamicSharedMemorySize, SMEM_TOTAL);

    const int M = NNODES;

    // launch 1: all weight transposes (batched)
    transpose_cvt4<<<dim3(32, 32, 4), dim3(32, 8)>>>(
        W1, wts + O_W1T, 512, 512,  W2, wts + O_W2T, 512, 512,
        W3, wts + O_W3T, 512, 1024, Wf, wts + O_WFT, 1024, 151);
    // launch 2: adj (x 2^14) + x -> fp16 (x lands in bufA)
    cvt_both_kernel<<<8192, 256>>>((const float4*)adj, (__half2*)adjh, (size_t)M * M / 4,
                                   (const float4*)x, (__half2*)bufA, (size_t)M * 512 / 4);

    // launch 3 — F1: bufB = (x @ W1)^T             [512 x 10000]
    tc_gemm<1, 0, 0, 0, 0><<<gmk(M, 512), 128, SMEM_TOTAL>>>(bufA, wts + O_W1T, nullptr, bufB, M, 512, 512);
    // launch 4 — G1: bufA = relu(adj @ P1 + b1)    [10000 x 512]   (ncu)
    tc_gemm<0, 1, 1, 1, 0><<<gmk(M, 512), 128, SMEM_TOTAL>>>(adjh, bufB, b1, bufA, M, 512, M);
    // F2: bufB = (H1 @ W2)^T                       [512 x 10000]
    tc_gemm<1, 0, 0, 0, 0><<<gmk(M, 512), 128, SMEM_TOTAL>>>(bufA, wts + O_W2T, nullptr, bufB, M, 512, 512);
    // G2: bufA = relu(adj @ P2 + b2)^T             [512 x 10000]  (TRANS write)
    tc_gemm<1, 1, 1, 1, 0><<<gmk(M, 512), 128, SMEM_TOTAL>>>(adjh, bufB, b2, bufA, M, 512, M);
    // G3': bufB = adj @ H2                         [10000 x 512]  (assoc. trick)
    tc_gemm<0, 0, 0, 1, 0><<<gmk(M, 512), 128, SMEM_TOTAL>>>(adjh, bufA, nullptr, bufB, M, 512, M);
    // F3': bufA = relu(Q @ W3 + b3)                [10000 x 1024]
    tc_gemm<0, 1, 1, 0, 0><<<gmk(M, 1024), 128, SMEM_TOTAL>>>(bufB, wts + O_W3T, b3, bufA, M, 1024, 512);
    // F4: out = H3 @ Wf + bf                       [10000 x 151] fp32
    tc_gemm<0, 1, 0, 0, 1><<<gmk(M, 151), 128, SMEM_TOTAL>>>(bufA, wts + O_WFT, bf, out, M, 151, 1024);
}